// round 8
// baseline (speedup 1.0000x reference)
#include <cuda_runtime.h>
#include <cuda_bf16.h>
#include <math.h>
#include <stdint.h>

#define BB 2
#define SS 2048
#define HH 16
#define DK 64
#define DM 1024
#define NQ (BB*SS)
#define INV_T 0.125f
#define NEGV -1000000000.0f

typedef __nv_bfloat16 bf;

// ---------------- scratch (static device allocations only) ----------------
__device__ bf g_xh[(size_t)NQ*DM],  g_xl[(size_t)NQ*DM];
__device__ bf g_wqh[(size_t)DM*DM], g_wql[(size_t)DM*DM];
__device__ bf g_wkh[(size_t)DM*DM], g_wkl[(size_t)DM*DM];
__device__ bf g_wvh[(size_t)DM*DM], g_wvl[(size_t)DM*DM];
__device__ bf g_wfh[(size_t)DM*DM], g_wfl[(size_t)DM*DM];
__device__ bf g_qh[(size_t)BB*HH*SS*DK], g_ql[(size_t)BB*HH*SS*DK];
__device__ bf g_kh[(size_t)BB*HH*SS*DK], g_kl[(size_t)BB*HH*SS*DK];
__device__ bf g_vh[(size_t)BB*HH*SS*DK], g_vl[(size_t)BB*HH*SS*DK];
__device__ bf g_vTh[(size_t)BB*HH*DK*SS];
__device__ bf g_oh[(size_t)NQ*DM], g_ol[(size_t)NQ*DM];
__device__ float g_tmp[(size_t)NQ*DM];
__device__ float g_attn_fb[(size_t)BB*HH*SS*SS];   // fallback if attn not in d_out

// ---------------- helpers -------------------------------------------------
__device__ __forceinline__ void mma16816(float c[4], const uint32_t a[4], const uint32_t b[2]) {
    asm volatile(
        "mma.sync.aligned.m16n8k16.row.col.f32.bf16.bf16.f32 "
        "{%0,%1,%2,%3},{%4,%5,%6,%7},{%8,%9},{%0,%1,%2,%3};\n"
        : "+f"(c[0]), "+f"(c[1]), "+f"(c[2]), "+f"(c[3])
        : "r"(a[0]), "r"(a[1]), "r"(a[2]), "r"(a[3]), "r"(b[0]), "r"(b[1]));
}

__device__ __forceinline__ void splitf(float v, bf& h, bf& l) {
    h = __float2bfloat16(v);
    l = __float2bfloat16(v - __bfloat162float(h));
}

__device__ __forceinline__ void split_pair(float a, float b, uint32_t& ph, uint32_t& pl) {
    bf ha, hb, la, lb;
    splitf(a, ha, la);
    splitf(b, hb, lb);
    ph = (uint32_t)__bfloat16_as_ushort(ha) | ((uint32_t)__bfloat16_as_ushort(hb) << 16);
    pl = (uint32_t)__bfloat16_as_ushort(la) | ((uint32_t)__bfloat16_as_ushort(lb) << 16);
}

__device__ __forceinline__ uint32_t pack_bf(float a, float b) {
    __nv_bfloat162 p = __floats2bfloat162_rn(a, b);
    return *reinterpret_cast<uint32_t*>(&p);
}

// ---------------- prep: split X into bf16 hi/lo ---------------------------
__global__ __launch_bounds__(256) void k_split(const float* __restrict__ in,
                                               bf* __restrict__ hi, bf* __restrict__ lo)
{
    int i = blockIdx.x * 256 + threadIdx.x;
    float4 v = ((const float4*)in)[i];
    uint32_t h01, l01, h23, l23;
    split_pair(v.x, v.y, h01, l01);
    split_pair(v.z, v.w, h23, l23);
    ((uint2*)hi)[i] = make_uint2(h01, h23);
    ((uint2*)lo)[i] = make_uint2(l01, l23);
}

// ---------------- prep: transpose + split W: W[k][n] -> T[n][k] ----------
__global__ __launch_bounds__(256) void k_wT(const float* __restrict__ W,
                                            bf* __restrict__ Th, bf* __restrict__ Tl)
{
    __shared__ bf sh[32][33], sl[32][33];
    int tx = threadIdx.x, ty = threadIdx.y;          // (32,8)
    int n0 = blockIdx.x * 32, k0 = blockIdx.y * 32;
    #pragma unroll
    for (int i = 0; i < 4; i++) {
        int k = k0 + ty + i * 8;
        float v = W[(size_t)k * DM + n0 + tx];
        splitf(v, sh[ty + i*8][tx], sl[ty + i*8][tx]);
    }
    __syncthreads();
    #pragma unroll
    for (int i = 0; i < 4; i++) {
        int n = n0 + ty + i * 8;
        Th[(size_t)n * DM + k0 + tx] = sh[tx][ty + i*8];
        Tl[(size_t)n * DM + k0 + tx] = sl[tx][ty + i*8];
    }
}

// ---------------- prep: transpose V hi -> vT[bh][d][s] -------------------
__global__ __launch_bounds__(256) void k_vT(const bf* __restrict__ vh,
                                            bf* __restrict__ vTh)
{
    __shared__ bf th[32][33];
    int tx = threadIdx.x, ty = threadIdx.y;          // (32,8)
    int s0 = blockIdx.x * 32, d0 = blockIdx.y * 32, bh = blockIdx.z;
    #pragma unroll
    for (int i = 0; i < 4; i++) {
        int s = s0 + ty + i * 8;
        th[ty + i*8][tx] = vh[((size_t)bh * SS + s) * DK + d0 + tx];
    }
    __syncthreads();
    #pragma unroll
    for (int i = 0; i < 4; i++) {
        int d = d0 + ty + i * 8;
        vTh[((size_t)bh * DK + d) * SS + s0 + tx] = th[tx][ty + i*8];
    }
}

// ---------------- GEMM (split-bf16, 3 MMA terms): projections -------------
__global__ __launch_bounds__(256) void gemm_proj_mma(
    const bf* __restrict__ ah_g, const bf* __restrict__ al_g,
    const bf* __restrict__ bh_g, const bf* __restrict__ bl_g,
    bf* __restrict__ ch_g, bf* __restrict__ cl_g)
{
    __shared__ bf Ah[128][40], Al[128][40], Bh[64][40], Bl[64][40];
    int tid = threadIdx.x;
    int w = tid >> 5, lane = tid & 31;
    int g = lane >> 2, t = lane & 3;
    int wm = w >> 1, wn = w & 1;
    int row0 = blockIdx.y * 128, col0 = blockIdx.x * 64;
    float acc[2][4][4] = {};
    for (int k0 = 0; k0 < DM; k0 += 32) {
        #pragma unroll
        for (int j = 0; j < 2; j++) {
            int idx = tid + j * 256;
            int r = idx >> 2, c = (idx & 3) * 8;
            *(uint4*)&Ah[r][c] = *(const uint4*)&ah_g[(size_t)(row0 + r) * DM + k0 + c];
            *(uint4*)&Al[r][c] = *(const uint4*)&al_g[(size_t)(row0 + r) * DM + k0 + c];
        }
        {
            int r = tid >> 2, c = (tid & 3) * 8;
            *(uint4*)&Bh[r][c] = *(const uint4*)&bh_g[(size_t)(col0 + r) * DM + k0 + c];
            *(uint4*)&Bl[r][c] = *(const uint4*)&bl_g[(size_t)(col0 + r) * DM + k0 + c];
        }
        __syncthreads();
        #pragma unroll
        for (int ks = 0; ks < 2; ks++) {
            int kc = ks * 16 + 2 * t;
            uint32_t a_h[2][4], a_l[2][4], b_h[4][2], b_l[4][2];
            #pragma unroll
            for (int mt = 0; mt < 2; mt++) {
                int m = wm * 32 + mt * 16 + g;
                a_h[mt][0] = *(uint32_t*)&Ah[m][kc];
                a_h[mt][1] = *(uint32_t*)&Ah[m + 8][kc];
                a_h[mt][2] = *(uint32_t*)&Ah[m][kc + 8];
                a_h[mt][3] = *(uint32_t*)&Ah[m + 8][kc + 8];
                a_l[mt][0] = *(uint32_t*)&Al[m][kc];
                a_l[mt][1] = *(uint32_t*)&Al[m + 8][kc];
                a_l[mt][2] = *(uint32_t*)&Al[m][kc + 8];
                a_l[mt][3] = *(uint32_t*)&Al[m + 8][kc + 8];
            }
            #pragma unroll
            for (int nt = 0; nt < 4; nt++) {
                int n = wn * 32 + nt * 8 + g;
                b_h[nt][0] = *(uint32_t*)&Bh[n][kc];
                b_h[nt][1] = *(uint32_t*)&Bh[n][kc + 8];
                b_l[nt][0] = *(uint32_t*)&Bl[n][kc];
                b_l[nt][1] = *(uint32_t*)&Bl[n][kc + 8];
            }
            #pragma unroll
            for (int mt = 0; mt < 2; mt++)
                #pragma unroll
                for (int nt = 0; nt < 4; nt++) {
                    mma16816(acc[mt][nt], a_h[mt], b_h[nt]);
                    mma16816(acc[mt][nt], a_h[mt], b_l[nt]);
                    mma16816(acc[mt][nt], a_l[mt], b_h[nt]);
                }
        }
        __syncthreads();
    }
    #pragma unroll
    for (int mt = 0; mt < 2; mt++)
        #pragma unroll
        for (int nt = 0; nt < 4; nt++) {
            int row = row0 + wm * 32 + mt * 16 + g;
            int col = col0 + wn * 32 + nt * 8 + 2 * t;
            int h = col >> 6, d = col & 63;
            int bi = row >> 11, s = row & 2047;
            size_t base = (((size_t)bi * HH + h) * SS + s) * DK + d;
            uint32_t ph, pl;
            split_pair(acc[mt][nt][0], acc[mt][nt][1], ph, pl);
            *(uint32_t*)&ch_g[base] = ph;
            *(uint32_t*)&cl_g[base] = pl;
            size_t base8 = (((size_t)bi * HH + h) * SS + s + 8) * DK + d;
            split_pair(acc[mt][nt][2], acc[mt][nt][3], ph, pl);
            *(uint32_t*)&ch_g[base8] = ph;
            *(uint32_t*)&cl_g[base8] = pl;
        }
}

// ---------------- GEMM fc: tmp = O @ Wfc + resid (fp32 out) ---------------
__global__ __launch_bounds__(256) void gemm_fc_mma(
    const bf* __restrict__ ah_g, const bf* __restrict__ al_g,
    const bf* __restrict__ bh_g, const bf* __restrict__ bl_g,
    const float* __restrict__ resid, float* __restrict__ out)
{
    __shared__ bf Ah[128][40], Al[128][40], Bh[64][40], Bl[64][40];
    int tid = threadIdx.x;
    int w = tid >> 5, lane = tid & 31;
    int g = lane >> 2, t = lane & 3;
    int wm = w >> 1, wn = w & 1;
    int row0 = blockIdx.y * 128, col0 = blockIdx.x * 64;
    float acc[2][4][4] = {};
    for (int k0 = 0; k0 < DM; k0 += 32) {
        #pragma unroll
        for (int j = 0; j < 2; j++) {
            int idx = tid + j * 256;
            int r = idx >> 2, c = (idx & 3) * 8;
            *(uint4*)&Ah[r][c] = *(const uint4*)&ah_g[(size_t)(row0 + r) * DM + k0 + c];
            *(uint4*)&Al[r][c] = *(const uint4*)&al_g[(size_t)(row0 + r) * DM + k0 + c];
        }
        {
            int r = tid >> 2, c = (tid & 3) * 8;
            *(uint4*)&Bh[r][c] = *(const uint4*)&bh_g[(size_t)(col0 + r) * DM + k0 + c];
            *(uint4*)&Bl[r][c] = *(const uint4*)&bl_g[(size_t)(col0 + r) * DM + k0 + c];
        }
        __syncthreads();
        #pragma unroll
        for (int ks = 0; ks < 2; ks++) {
            int kc = ks * 16 + 2 * t;
            uint32_t a_h[2][4], a_l[2][4], b_h[4][2], b_l[4][2];
            #pragma unroll
            for (int mt = 0; mt < 2; mt++) {
                int m = wm * 32 + mt * 16 + g;
                a_h[mt][0] = *(uint32_t*)&Ah[m][kc];
                a_h[mt][1] = *(uint32_t*)&Ah[m + 8][kc];
                a_h[mt][2] = *(uint32_t*)&Ah[m][kc + 8];
                a_h[mt][3] = *(uint32_t*)&Ah[m + 8][kc + 8];
                a_l[mt][0] = *(uint32_t*)&Al[m][kc];
                a_l[mt][1] = *(uint32_t*)&Al[m + 8][kc];
                a_l[mt][2] = *(uint32_t*)&Al[m][kc + 8];
                a_l[mt][3] = *(uint32_t*)&Al[m + 8][kc + 8];
            }
            #pragma unroll
            for (int nt = 0; nt < 4; nt++) {
                int n = wn * 32 + nt * 8 + g;
                b_h[nt][0] = *(uint32_t*)&Bh[n][kc];
                b_h[nt][1] = *(uint32_t*)&Bh[n][kc + 8];
                b_l[nt][0] = *(uint32_t*)&Bl[n][kc];
                b_l[nt][1] = *(uint32_t*)&Bl[n][kc + 8];
            }
            #pragma unroll
            for (int mt = 0; mt < 2; mt++)
                #pragma unroll
                for (int nt = 0; nt < 4; nt++) {
                    mma16816(acc[mt][nt], a_h[mt], b_h[nt]);
                    mma16816(acc[mt][nt], a_h[mt], b_l[nt]);
                    mma16816(acc[mt][nt], a_l[mt], b_h[nt]);
                }
        }
        __syncthreads();
    }
    #pragma unroll
    for (int mt = 0; mt < 2; mt++)
        #pragma unroll
        for (int nt = 0; nt < 4; nt++) {
            int row = row0 + wm * 32 + mt * 16 + g;
            int col = col0 + wn * 32 + nt * 8 + 2 * t;
            float2 rv = *(const float2*)&resid[(size_t)row * DM + col];
            *(float2*)&out[(size_t)row * DM + col] =
                make_float2(acc[mt][nt][0] + rv.x, acc[mt][nt][1] + rv.y);
            rv = *(const float2*)&resid[(size_t)(row + 8) * DM + col];
            *(float2*)&out[(size_t)(row + 8) * DM + col] =
                make_float2(acc[mt][nt][2] + rv.x, acc[mt][nt][3] + rv.y);
        }
}

// ------- fused attention: phase A (S raw + m/l), phase B (norm + PV) ------
// Block handles 64 q rows of one (b,h). 8 warps.
// Phase A layout: wq=w>>2 (2) x wk=w&3 (4), warp tile 32q x 16k. Q frags hoisted.
// Phase B layout: wq x wd=w&3, warp tile 32q x 16d. P*V 1-term bf16.
__global__ __launch_bounds__(256, 2) void attn_fused(
    const bf* __restrict__ qh, const bf* __restrict__ ql,
    const bf* __restrict__ kh, const bf* __restrict__ kl,
    const bf* __restrict__ vTh,
    const int* __restrict__ mask, float* __restrict__ attn,
    bf* __restrict__ oh, bf* __restrict__ ol)
{
    __shared__ bf S1[64][72];                       // Qh stage -> Kh -> P(bf16)
    __shared__ bf S2[64][72];                       // Ql stage -> Kl -> V^T(hi)
    __shared__ float red[4][64];
    __shared__ float m_s[64], l_s[64], mold[64], li_s[64];
    int tid = threadIdx.x;
    int w = tid >> 5, lane = tid & 31;
    int g = lane >> 2, t = lane & 3;
    int wq = w >> 2, wk = w & 3;
    int q0 = blockIdx.x * 64, bh = blockIdx.y;
    int b = bh >> 4, h = bh & 15;

    // ---- stage Q, extract fragments into registers ----
    const bf* qhb = qh + ((size_t)bh * SS + q0) * DK;
    const bf* qlb = ql + ((size_t)bh * SS + q0) * DK;
    #pragma unroll
    for (int j = 0; j < 2; j++) {
        int idx = tid + j * 256;
        int r = idx >> 3, c = (idx & 7) * 8;
        *(uint4*)&S1[r][c] = *(const uint4*)&qhb[(size_t)r * DK + c];
        *(uint4*)&S2[r][c] = *(const uint4*)&qlb[(size_t)r * DK + c];
    }
    if (tid < 64) { m_s[tid] = -INFINITY; l_s[tid] = 0.0f; }
    __syncthreads();
    uint32_t qfh[4][2][4], qfl[4][2][4];
    #pragma unroll
    for (int ks = 0; ks < 4; ks++) {
        int kc = ks * 16 + 2 * t;
        #pragma unroll
        for (int mt = 0; mt < 2; mt++) {
            int m = wq * 32 + mt * 16 + g;
            qfh[ks][mt][0] = *(uint32_t*)&S1[m][kc];
            qfh[ks][mt][1] = *(uint32_t*)&S1[m + 8][kc];
            qfh[ks][mt][2] = *(uint32_t*)&S1[m][kc + 8];
            qfh[ks][mt][3] = *(uint32_t*)&S1[m + 8][kc + 8];
            qfl[ks][mt][0] = *(uint32_t*)&S2[m][kc];
            qfl[ks][mt][1] = *(uint32_t*)&S2[m + 8][kc];
            qfl[ks][mt][2] = *(uint32_t*)&S2[m][kc + 8];
            qfl[ks][mt][3] = *(uint32_t*)&S2[m + 8][kc + 8];
        }
    }

    // ---- phase A: 32 key tiles ----
    for (int kt = 0; kt < 32; kt++) {
        int k0 = kt * 64;
        __syncthreads();                             // frags/prior-iter reads done
        const bf* khb = kh + ((size_t)bh * SS + k0) * DK;
        const bf* klb = kl + ((size_t)bh * SS + k0) * DK;
        #pragma unroll
        for (int j = 0; j < 2; j++) {
            int idx = tid + j * 256;
            int r = idx >> 3, c = (idx & 7) * 8;
            *(uint4*)&S1[r][c] = *(const uint4*)&khb[(size_t)r * DK + c];
            *(uint4*)&S2[r][c] = *(const uint4*)&klb[(size_t)r * DK + c];
        }
        __syncthreads();
        float acc[2][2][4] = {};
        #pragma unroll
        for (int ks = 0; ks < 4; ks++) {
            int kc = ks * 16 + 2 * t;
            uint32_t b_h[2][2], b_l[2][2];
            #pragma unroll
            for (int nt = 0; nt < 2; nt++) {
                int n = wk * 16 + nt * 8 + g;
                b_h[nt][0] = *(uint32_t*)&S1[n][kc];
                b_h[nt][1] = *(uint32_t*)&S1[n][kc + 8];
                b_l[nt][0] = *(uint32_t*)&S2[n][kc];
                b_l[nt][1] = *(uint32_t*)&S2[n][kc + 8];
            }
            #pragma unroll
            for (int mt = 0; mt < 2; mt++)
                #pragma unroll
                for (int nt = 0; nt < 2; nt++) {
                    mma16816(acc[mt][nt], qfh[ks][mt], b_h[nt]);
                    mma16816(acc[mt][nt], qfh[ks][mt], b_l[nt]);
                    mma16816(acc[mt][nt], qfl[ks][mt], b_h[nt]);
                }
        }
        // scale + mask + raw store + row max
        float rmax[2][2];
        rmax[0][0] = rmax[0][1] = rmax[1][0] = rmax[1][1] = -INFINITY;
        #pragma unroll
        for (int mt = 0; mt < 2; mt++) {
            int q = q0 + wq * 32 + mt * 16 + g;
            #pragma unroll
            for (int nt = 0; nt < 2; nt++) {
                int col = k0 + wk * 16 + nt * 8 + 2 * t;
                int2 m0 = *(const int2*)&mask[((size_t)(b * SS + q)) * SS + col];
                int2 m1 = *(const int2*)&mask[((size_t)(b * SS + q + 8)) * SS + col];
                float s0 = m0.x ? acc[mt][nt][0] * INV_T : NEGV;
                float s1 = m0.y ? acc[mt][nt][1] * INV_T : NEGV;
                float s2 = m1.x ? acc[mt][nt][2] * INV_T : NEGV;
                float s3 = m1.y ? acc[mt][nt][3] * INV_T : NEGV;
                *(float2*)&attn[((size_t)bh * SS + q) * SS + col]     = make_float2(s0, s1);
                *(float2*)&attn[((size_t)bh * SS + q + 8) * SS + col] = make_float2(s2, s3);
                acc[mt][nt][0] = s0; acc[mt][nt][1] = s1;
                acc[mt][nt][2] = s2; acc[mt][nt][3] = s3;
                rmax[mt][0] = fmaxf(rmax[mt][0], fmaxf(s0, s1));
                rmax[mt][1] = fmaxf(rmax[mt][1], fmaxf(s2, s3));
            }
        }
        #pragma unroll
        for (int o = 1; o < 4; o <<= 1) {
            #pragma unroll
            for (int mt = 0; mt < 2; mt++) {
                rmax[mt][0] = fmaxf(rmax[mt][0], __shfl_xor_sync(0xffffffffu, rmax[mt][0], o));
                rmax[mt][1] = fmaxf(rmax[mt][1], __shfl_xor_sync(0xffffffffu, rmax[mt][1], o));
            }
        }
        if (t == 0) {
            #pragma unroll
            for (int mt = 0; mt < 2; mt++) {
                red[wk][wq * 32 + mt * 16 + g]     = rmax[mt][0];
                red[wk][wq * 32 + mt * 16 + g + 8] = rmax[mt][1];
            }
        }
        __syncthreads();
        if (tid < 64) {
            float mo = m_s[tid];
            float mn = fmaxf(fmaxf(red[0][tid], red[1][tid]), fmaxf(red[2][tid], red[3][tid]));
            mn = fmaxf(mn, mo);
            mold[tid] = mo;
            m_s[tid] = mn;
        }
        __syncthreads();
        float psum[2][2] = {};
        #pragma unroll
        for (int mt = 0; mt < 2; mt++) {
            int lr = wq * 32 + mt * 16 + g;
            float mr0 = m_s[lr], mr1 = m_s[lr + 8];
            #pragma unroll
            for (int nt = 0; nt < 2; nt++) {
                psum[mt][0] += __expf(acc[mt][nt][0] - mr0) + __expf(acc[mt][nt][1] - mr0);
                psum[mt][1] += __expf(acc[mt][nt][2] - mr1) + __expf(acc[mt][nt][3] - mr1);
            }
        }
        #pragma unroll
        for (int o = 1; o < 4; o <<= 1) {
            #pragma unroll
            for (int mt = 0; mt < 2; mt++) {
                psum[mt][0] += __shfl_xor_sync(0xffffffffu, psum[mt][0], o);
                psum[mt][1] += __shfl_xor_sync(0xffffffffu, psum[mt][1], o);
            }
        }
        if (t == 0) {
            #pragma unroll
            for (int mt = 0; mt < 2; mt++) {
                red[wk][wq * 32 + mt * 16 + g]     = psum[mt][0];
                red[wk][wq * 32 + mt * 16 + g + 8] = psum[mt][1];
            }
        }
        __syncthreads();
        if (tid < 64) {
            l_s[tid] = l_s[tid] * __expf(mold[tid] - m_s[tid])
                     + red[0][tid] + red[1][tid] + red[2][tid] + red[3][tid];
        }
    }
    __syncthreads();
    if (tid < 64) li_s[tid] = 1.0f / l_s[tid];

    // ---- phase B: normalize (raw S now L2-hot) + P@V ----
    int wd = w & 3;
    float acc[2][2][4] = {};
    for (int kt = 0; kt < 32; kt++) {
        int k0 = kt * 64;
        __syncthreads();                             // prior-iter frag reads done
        #pragma unroll
        for (int j = 0; j < 4; j++) {
            int idx = tid + j * 256;
            int r = idx >> 4, c4 = (idx & 15) * 4;
            float* ap = &attn[((size_t)bh * SS + q0 + r) * SS + k0 + c4];
            float4 v = *(float4*)ap;
            float mr = m_s[r], li = li_s[r];
            float p0 = __expf(v.x - mr) * li;
            float p1 = __expf(v.y - mr) * li;
            float p2 = __expf(v.z - mr) * li;
            float p3 = __expf(v.w - mr) * li;
            *(float4*)ap = make_float4(p0, p1, p2, p3);
            *(uint32_t*)&S1[r][c4]     = pack_bf(p0, p1);
            *(uint32_t*)&S1[r][c4 + 2] = pack_bf(p2, p3);
        }
        #pragma unroll
        for (int j = 0; j < 2; j++) {                // V^T tile: 64 d x 64 keys
            int idx = tid + j * 256;
            int r = idx >> 3, c = (idx & 7) * 8;
            *(uint4*)&S2[r][c] = *(const uint4*)&vTh[((size_t)bh * DK + r) * SS + k0 + c];
        }
        __syncthreads();
        #pragma unroll
        for (int ks = 0; ks < 4; ks++) {
            int kc = ks * 16 + 2 * t;
            uint32_t a_p[2][4], b_v[2][2];
            #pragma unroll
            for (int mt = 0; mt < 2; mt++) {
                int m = wq * 32 + mt * 16 + g;
                a_p[mt][0] = *(uint32_t*)&S1[m][kc];
                a_p[mt][1] = *(uint32_t*)&S1[m + 8][kc];
                a_p[mt][2] = *(uint32_t*)&S1[m][kc + 8];
                a_p[mt][3] = *(uint32_t*)&S1[m + 8][kc + 8];
            }
            #pragma unroll
            for (int nt = 0; nt < 2; nt++) {
                int n = wd * 16 + nt * 8 + g;
                b_v[nt][0] = *(uint32_t*)&S2[n][kc];
                b_v[nt][1] = *(uint32_t*)&S2[n][kc + 8];
            }
            #pragma unroll
            for (int mt = 0; mt < 2; mt++)
                #pragma unroll
                for (int nt = 0; nt < 2; nt++)
                    mma16816(acc[mt][nt], a_p[mt], b_v[nt]);
        }
    }
    // epilogue: O split to bf16 hi/lo, merged-head layout [b][s][h*64+d]
    #pragma unroll
    for (int mt = 0; mt < 2; mt++)
        #pragma unroll
        for (int nt = 0; nt < 2; nt++) {
            int sg = q0 + wq * 32 + mt * 16 + g;
            int dcol = wd * 16 + nt * 8 + 2 * t;
            size_t base = ((size_t)(b * SS + sg)) * DM + h * DK + dcol;
            uint32_t ph, pl;
            split_pair(acc[mt][nt][0], acc[mt][nt][1], ph, pl);
            *(uint32_t*)&oh[base] = ph;
            *(uint32_t*)&ol[base] = pl;
            size_t base8 = ((size_t)(b * SS + sg + 8)) * DM + h * DK + dcol;
            split_pair(acc[mt][nt][2], acc[mt][nt][3], ph, pl);
            *(uint32_t*)&oh[base8] = ph;
            *(uint32_t*)&ol[base8] = pl;
        }
}

// ---------------- LayerNorm: one row (1024) per block --------------------
__global__ __launch_bounds__(256) void ln_kernel(const float* __restrict__ xin,
                                                 const float* __restrict__ gamma,
                                                 const float* __restrict__ beta,
                                                 float* __restrict__ out)
{
    __shared__ float red[8];
    __shared__ float mu_s, rs_s;
    int row = blockIdx.x, tid = threadIdx.x;
    float4 v = *(const float4*)&xin[(size_t)row * DM + tid * 4];
    float s = v.x + v.y + v.z + v.w;
    #pragma unroll
    for (int o = 16; o > 0; o >>= 1) s += __shfl_down_sync(0xffffffffu, s, o);
    if ((tid & 31) == 0) red[tid >> 5] = s;
    __syncthreads();
    if (tid == 0) {
        float tt = 0;
        #pragma unroll
        for (int i = 0; i < 8; i++) tt += red[i];
        mu_s = tt * (1.0f / DM);
    }
    __syncthreads();
    float mu = mu_s;
    float dx0 = v.x - mu, dx1 = v.y - mu, dx2 = v.z - mu, dx3 = v.w - mu;
    float s2 = dx0*dx0 + dx1*dx1 + dx2*dx2 + dx3*dx3;
    #pragma unroll
    for (int o = 16; o > 0; o >>= 1) s2 += __shfl_down_sync(0xffffffffu, s2, o);
    if ((tid & 31) == 0) red[tid >> 5] = s2;
    __syncthreads();
    if (tid == 0) {
        float tt = 0;
        #pragma unroll
        for (int i = 0; i < 8; i++) tt += red[i];
        rs_s = rsqrtf(tt * (1.0f / DM) + 1e-6f);
    }
    __syncthreads();
    float rs = rs_s;
    float4 gmv = *(const float4*)&gamma[tid * 4];
    float4 btv = *(const float4*)&beta[tid * 4];
    float4 o4;
    o4.x = dx0 * rs * gmv.x + btv.x;
    o4.y = dx1 * rs * gmv.y + btv.y;
    o4.z = dx2 * rs * gmv.z + btv.z;
    o4.w = dx3 * rs * gmv.w + btv.w;
    *(float4*)&out[(size_t)row * DM + tid * 4] = o4;
}

// --------------------------------------------------------------------------
extern "C" void kernel_launch(void* const* d_in, const int* in_sizes, int n_in,
                              void* d_out, int out_size)
{
    const float* qkv   = (const float*)d_in[0];
    const int*   mask  = (const int*)  d_in[1];
    const float* w_qs  = (const float*)d_in[2];
    const float* w_ks  = (const float*)d_in[3];
    const float* w_vs  = (const float*)d_in[4];
    const float* w_fc  = (const float*)d_in[5];
    const float* gamma = (const float*)d_in[6];
    const float* beta  = (const float*)d_in[7];
    float* out = (float*)d_out;

    const size_t out_elems  = (size_t)NQ * DM;
    const size_t attn_elems = (size_t)BB * HH * SS * SS;

    bf *xh, *xl, *wqh, *wql, *wkh, *wkl, *wvh, *wvl, *wfh, *wfl;
    bf *qh, *ql, *kh, *kl, *vh, *vl, *vth, *oh, *ol;
    float *tb, *attn;
    cudaGetSymbolAddress((void**)&xh,  g_xh);  cudaGetSymbolAddress((void**)&xl,  g_xl);
    cudaGetSymbolAddress((void**)&wqh, g_wqh); cudaGetSymbolAddress((void**)&wql, g_wql);
    cudaGetSymbolAddress((void**)&wkh, g_wkh); cudaGetSymbolAddress((void**)&wkl, g_wkl);
    cudaGetSymbolAddress((void**)&wvh, g_wvh); cudaGetSymbolAddress((void**)&wvl, g_wvl);
    cudaGetSymbolAddress((void**)&wfh, g_wfh); cudaGetSymbolAddress((void**)&wfl, g_wfl);
    cudaGetSymbolAddress((void**)&qh,  g_qh);  cudaGetSymbolAddress((void**)&ql,  g_ql);
    cudaGetSymbolAddress((void**)&kh,  g_kh);  cudaGetSymbolAddress((void**)&kl,  g_kl);
    cudaGetSymbolAddress((void**)&vh,  g_vh);  cudaGetSymbolAddress((void**)&vl,  g_vl);
    cudaGetSymbolAddress((void**)&vth, g_vTh);
    cudaGetSymbolAddress((void**)&oh,  g_oh);  cudaGetSymbolAddress((void**)&ol,  g_ol);
    cudaGetSymbolAddress((void**)&tb,  g_tmp);
    if ((size_t)out_size >= out_elems + attn_elems) {
        attn = out + out_elems;
    } else {
        cudaGetSymbolAddress((void**)&attn, g_attn_fb);
    }

    // prep: split X, transpose+split weights
    k_split<<<4096, 256>>>(qkv, xh, xl);
    dim3 wtg(32, 32), wtb(32, 8);
    k_wT<<<wtg, wtb>>>(w_qs, wqh, wql);
    k_wT<<<wtg, wtb>>>(w_ks, wkh, wkl);
    k_wT<<<wtg, wtb>>>(w_vs, wvh, wvl);
    k_wT<<<wtg, wtb>>>(w_fc, wfh, wfl);

    // projections (tensor-core)
    dim3 ggrid(DM / 64, NQ / 128);       // (16, 32)
    gemm_proj_mma<<<ggrid, 256>>>(xh, xl, wqh, wql, qh, ql);
    gemm_proj_mma<<<ggrid, 256>>>(xh, xl, wkh, wkl, kh, kl);
    gemm_proj_mma<<<ggrid, 256>>>(xh, xl, wvh, wvl, vh, vl);
    k_vT<<<dim3(SS / 32, DK / 32, BB * HH), wtb>>>(vh, vth);

    // fused attention (tensor-core)
    dim3 agrid(SS / 64, BB * HH);        // (32, 32)
    attn_fused<<<agrid, 256>>>(qh, ql, kh, kl, vth, mask, attn, oh, ol);

    // output projection + residual, then LayerNorm
    gemm_fc_mma<<<ggrid, 256>>>(oh, ol, wfh, wfl, qkv, tb);
    ln_kernel<<<NQ, 256>>>(tb, gamma, beta, out);
}